// round 9
// baseline (speedup 1.0000x reference)
#include <cuda_runtime.h>
#include <cuda_fp16.h>
#include <math.h>
#include <stdint.h>

#define D_MODEL 2048
#define N_HEADS 16
#define DPH     128
#define D_FF    8192
#define BATCH   2
#define SEQ     2048
#define MROWS   (BATCH*SEQ)
#define HALFD   (DPH/2)
#define BH      (BATCH*N_HEADS)

// ---------------- scratch (static device arrays; no cudaMalloc) ----------------
__device__ __half g_xn16[(size_t)MROWS*D_MODEL];
__device__ float  g_qkv [(size_t)3*MROWS*D_MODEL];
__device__ __half g_q16 [(size_t)MROWS*D_MODEL];
__device__ __half g_k16 [(size_t)MROWS*D_MODEL];
__device__ __half g_v16t[(size_t)BH*DPH*SEQ];
__device__ float  g_logits[(size_t)BH*SEQ*SEQ];
__device__ __half g_p16 [(size_t)BH*SEQ*SEQ];
__device__ __half g_av16[(size_t)MROWS*D_MODEL];
__device__ float  g_ao  [(size_t)MROWS*D_MODEL];
__device__ __half g_h16 [(size_t)MROWS*D_FF];
__device__ __half g_wqkvt[(size_t)3*D_MODEL*D_MODEL];
__device__ __half g_wot [(size_t)D_MODEL*D_MODEL];
__device__ __half g_wfit[(size_t)D_FF*D_MODEL];
__device__ __half g_wfot[(size_t)D_MODEL*D_FF];
__device__ float2 g_sincos[(size_t)SEQ*HALFD];

// ---------------- family-portable PTX helpers -----------------------------------
__device__ __forceinline__ uint32_t smem_u32(const void* p) {
    uint32_t a;
    asm("{ .reg .u64 t; cvta.to.shared.u64 t, %1; cvt.u32.u64 %0, t; }" : "=r"(a) : "l"(p));
    return a;
}
__device__ __forceinline__ void cp_async16(uint32_t saddr, const void* gptr) {
    asm volatile("cp.async.cg.shared.global [%0], [%1], 16;" :: "r"(saddr), "l"(gptr));
}
__device__ __forceinline__ void cp_commit() {
    asm volatile("cp.async.commit_group;" ::: "memory");
}
template<int N>
__device__ __forceinline__ void cp_wait() {
    asm volatile("cp.async.wait_group %0;" :: "n"(N) : "memory");
}
__device__ __forceinline__ void ldsm_x4(uint32_t& r0, uint32_t& r1, uint32_t& r2, uint32_t& r3,
                                        uint32_t addr) {
    asm volatile("ldmatrix.sync.aligned.m8n8.x4.shared.b16 {%0,%1,%2,%3}, [%4];"
        : "=r"(r0), "=r"(r1), "=r"(r2), "=r"(r3) : "r"(addr));
}
__device__ __forceinline__ void mma16816(float& c0, float& c1, float& c2, float& c3,
                                         uint32_t a0, uint32_t a1, uint32_t a2, uint32_t a3,
                                         uint32_t b0, uint32_t b1) {
    asm volatile("mma.sync.aligned.m16n8k16.row.col.f32.f16.f16.f32 "
        "{%0,%1,%2,%3}, {%4,%5,%6,%7}, {%8,%9}, {%0,%1,%2,%3};"
        : "+f"(c0), "+f"(c1), "+f"(c2), "+f"(c3)
        : "r"(a0), "r"(a1), "r"(a2), "r"(a3), "r"(b0), "r"(b1));
}

// ---------------- small kernels -------------------------------------------------
__global__ void sincos_kernel() {
    int idx = blockIdx.x * blockDim.x + threadIdx.x;
    if (idx >= SEQ * HALFD) return;
    int t = idx / HALFD, i = idx % HALFD;
    double invf = pow(10000.0, -(2.0 * i) / (double)DPH);
    double ang  = (double)t * invf;
    g_sincos[idx] = make_float2((float)sin(ang), (float)cos(ang));
}

__global__ void layernorm_kernel(const float* __restrict__ x,
                                 const float* __restrict__ scale,
                                 const float* __restrict__ offset) {
    int row = blockIdx.x;
    const float* xr = x + (size_t)row * D_MODEL;
    __half* o = g_xn16 + (size_t)row * D_MODEL;
    float s = 0.f, s2 = 0.f;
    for (int j = threadIdx.x; j < D_MODEL; j += blockDim.x) {
        float v = xr[j]; s += v; s2 += v * v;
    }
    __shared__ float red[64];
    #pragma unroll
    for (int off = 16; off; off >>= 1) {
        s  += __shfl_xor_sync(0xffffffffu, s,  off);
        s2 += __shfl_xor_sync(0xffffffffu, s2, off);
    }
    int wid = threadIdx.x >> 5, lid = threadIdx.x & 31;
    if (lid == 0) { red[wid] = s; red[wid + 32] = s2; }
    __syncthreads();
    if (threadIdx.x < 32) {
        int nw = blockDim.x >> 5;
        s  = (threadIdx.x < nw) ? red[threadIdx.x]      : 0.f;
        s2 = (threadIdx.x < nw) ? red[threadIdx.x + 32] : 0.f;
        #pragma unroll
        for (int off = 16; off; off >>= 1) {
            s  += __shfl_xor_sync(0xffffffffu, s,  off);
            s2 += __shfl_xor_sync(0xffffffffu, s2, off);
        }
        if (lid == 0) { red[0] = s; red[1] = s2; }
    }
    __syncthreads();
    float mean = red[0] / D_MODEL;
    float var  = red[1] / D_MODEL - mean * mean;
    float r    = rsqrtf(var + 1e-5f);
    for (int j = threadIdx.x; j < D_MODEL; j += blockDim.x)
        o[j] = __float2half(scale[j] * r * (xr[j] - mean) + offset[j]);
}

// rotary: fp32 q/k -> fp16 q16/k16
__global__ void rotary_kernel(const float* __restrict__ q, const float* __restrict__ k) {
    int idx = blockIdx.x * blockDim.x + threadIdx.x;
    if (idx >= MROWS * N_HEADS * HALFD) return;
    int half = idx % HALFD;
    int rest = idx / HALFD;
    int h    = rest % N_HEADS;
    int row  = rest / N_HEADS;
    int t    = row % SEQ;
    float2 sc = g_sincos[t * HALFD + half];
    size_t base = (size_t)row * D_MODEL + h * DPH + 2 * half;
    float q0 = q[base], q1 = q[base + 1];
    g_q16[base]     = __float2half(q0 * sc.y - q1 * sc.x);
    g_q16[base + 1] = __float2half(q1 * sc.y + q0 * sc.x);
    float k0 = k[base], k1 = k[base + 1];
    g_k16[base]     = __float2half(k0 * sc.y - k1 * sc.x);
    g_k16[base + 1] = __float2half(k1 * sc.y + k0 * sc.x);
}

// weight transpose+convert: in[R][C] fp32 -> out[C][R] fp16
__global__ void tconv_kernel(const float* __restrict__ in, __half* __restrict__ out,
                             int R, int C) {
    __shared__ float t[32][33];
    int bx = blockIdx.x * 32, by = blockIdx.y * 32;
    int tx = threadIdx.x, ty = threadIdx.y;
    #pragma unroll
    for (int i = 0; i < 4; i++)
        t[ty + i * 8][tx] = in[(size_t)(by + ty + i * 8) * C + bx + tx];
    __syncthreads();
    #pragma unroll
    for (int i = 0; i < 4; i++)
        out[(size_t)(bx + ty + i * 8) * R + by + tx] = __float2half(t[tx][ty + i * 8]);
}

// V transpose: fp32 [b*S+t][h*128+d] -> v16t [bh][d][t] fp16
__global__ void vtrans_kernel(const float* __restrict__ v) {
    __shared__ float t[32][33];
    int z = blockIdx.z, bb = z >> 4, hh = z & 15;
    int tb = blockIdx.x * 32, db = blockIdx.y * 32;
    int tx = threadIdx.x, ty = threadIdx.y;
    #pragma unroll
    for (int i = 0; i < 4; i++)
        t[ty + i * 8][tx] = v[(size_t)(bb * SEQ + tb + ty + i * 8) * D_MODEL + hh * DPH + db + tx];
    __syncthreads();
    #pragma unroll
    for (int i = 0; i < 4; i++)
        g_v16t[((size_t)z * DPH + db + ty + i * 8) * SEQ + tb + tx] = __float2half(t[tx][ty + i * 8]);
}

__device__ __forceinline__ float gelu_tanh(float x) {
    float x3 = x * x * x;
    float t = tanhf(0.7978845608028654f * (x + 0.044715f * x3));
    return 0.5f * x * (1.f + t);
}

// masked softmax: fp32 logits (+bias, causal) -> fp16 probs
// chunks fully beyond the diagonal are skipped (exp(-1e10) == 0 in fp32: exact)
__global__ __launch_bounds__(256)
void softmax_kernel(const float* __restrict__ attn_bias) {
    long long r = blockIdx.x;
    int i = (int)(r % SEQ);
    const float* row = g_logits + r * SEQ;
    __half* prow = g_p16 + r * SEQ;
    const float* brow = attn_bias + (size_t)i * SEQ;
    int tid = threadIdx.x;
    float vals[8];
    float mx = -INFINITY;
    #pragma unroll
    for (int l = 0; l < 8; l++) {
        int j = tid + l * 256;
        float v;
        if (l * 256 <= i) {                 // uniform per block: no divergence
            v = row[j] + brow[j];
            if (j > i) v += -1e10f;
        } else {
            v = -1e30f;                     // exp -> exactly 0
        }
        vals[l] = v;
        mx = fmaxf(mx, v);
    }
    __shared__ float red[32];
    #pragma unroll
    for (int off = 16; off; off >>= 1)
        mx = fmaxf(mx, __shfl_xor_sync(0xffffffffu, mx, off));
    int wid = tid >> 5, lid = tid & 31;
    if (lid == 0) red[wid] = mx;
    __syncthreads();
    if (tid < 32) {
        mx = (tid < 8) ? red[tid] : -INFINITY;
        #pragma unroll
        for (int off = 4; off; off >>= 1)
            mx = fmaxf(mx, __shfl_xor_sync(0xffffffffu, mx, off));
        if (lid == 0) red[0] = mx;
    }
    __syncthreads();
    mx = red[0];
    float sum = 0.f;
    #pragma unroll
    for (int l = 0; l < 8; l++) { vals[l] = expf(vals[l] - mx); sum += vals[l]; }
    #pragma unroll
    for (int off = 16; off; off >>= 1)
        sum += __shfl_xor_sync(0xffffffffu, sum, off);
    if (lid == 0) red[wid] = sum;
    __syncthreads();
    if (tid < 32) {
        sum = (tid < 8) ? red[tid] : 0.f;
        #pragma unroll
        for (int off = 4; off; off >>= 1)
            sum += __shfl_xor_sync(0xffffffffu, sum, off);
        if (lid == 0) red[0] = sum;
    }
    __syncthreads();
    float inv = 1.f / red[0];
    #pragma unroll
    for (int l = 0; l < 8; l++)
        prow[tid + l * 256] = __float2half(vals[l] * inv);
}

// ---------------- shared GEMM constants ------------------------------------------
#define SROW   80              // bytes per padded smem row (64B payload, 20-bank stride)

// ================= hgemm: 128x128 tile (PV path; proven in round 7) =============
// CAUSAL=1: A rows r only need K <= rowBase+128 (P[r][c]==0 for c>r) - exact clamp.
#define TILE_B (128 * SROW)
#define STAGE_B (2 * TILE_B)

template<int EPI, int CAUSAL, typename CT>
__global__ __launch_bounds__(256)
void hgemm(const __half* __restrict__ A, const __half* __restrict__ Bt,
           CT* __restrict__ C, const float* __restrict__ bias,
           const float* __restrict__ add,
           int K, int lda, int ldb, int ldc,
           long long sAb, long long sAh, long long sBb, long long sBh,
           long long sCb, long long sCh, int hdiv, float alpha) {
    __shared__ __align__(16) char smem[2 * STAGE_B];   // 40 KB
    const uint32_t sbase = smem_u32(smem);
    int tid = threadIdx.x, wid = tid >> 5, lid = tid & 31;

    int z = blockIdx.z, bb = z / hdiv, hh = z % hdiv;
    A  += bb * sAb + hh * sAh;
    Bt += bb * sBb + hh * sBh;
    C  += bb * sCb + hh * sCh;
    int rowBase = blockIdx.y * 128;
    int colBase = blockIdx.x * 128;

    int wm = (wid >> 2) * 64;
    int wn = (wid & 3) * 32;

    float acc[4][4][4];
    #pragma unroll
    for (int i = 0; i < 4; i++)
        #pragma unroll
        for (int j = 0; j < 4; j++)
            #pragma unroll
            for (int c = 0; c < 4; c++) acc[i][j][c] = 0.f;

    int Keff = CAUSAL ? min(K, rowBase + 128) : K;
    const int NC = Keff >> 5;
    auto stage_load = [&](int st, int k0) {
        uint32_t base = sbase + st * STAGE_B;
        #pragma unroll
        for (int l = 0; l < 4; l++) {
            int c = tid + l * 256;
            int r  = (c & 511) >> 2;
            int kc = c & 3;
            if (c < 512)
                cp_async16(base + r * SROW + kc * 16,
                           A + (size_t)(rowBase + r) * lda + k0 + kc * 8);
            else
                cp_async16(base + TILE_B + r * SROW + kc * 16,
                           Bt + (size_t)(colBase + r) * ldb + k0 + kc * 8);
        }
        cp_commit();
    };

    stage_load(0, 0);

    for (int i = 0; i < NC; i++) {
        __syncthreads();
        if (i + 1 < NC) { stage_load((i + 1) & 1, (i + 1) << 5); cp_wait<1>(); }
        else            { cp_wait<0>(); }
        __syncthreads();

        uint32_t abase = sbase + (i & 1) * STAGE_B;
        uint32_t bbase = abase + TILE_B;
        int which = lid >> 3, rim = lid & 7;

        #pragma unroll
        for (int ks = 0; ks < 2; ks++) {
            uint32_t a[4][4];
            #pragma unroll
            for (int mf = 0; mf < 4; mf++) {
                int r = wm + mf * 16 + ((which & 1) << 3) + rim;
                uint32_t addr = abase + r * SROW + ks * 32 + ((which >> 1) << 4);
                ldsm_x4(a[mf][0], a[mf][1], a[mf][2], a[mf][3], addr);
            }
            uint32_t b[4][2];
            #pragma unroll
            for (int np = 0; np < 2; np++) {
                int n = wn + np * 16 + ((which >> 1) << 3) + rim;
                uint32_t addr = bbase + n * SROW + ks * 32 + ((which & 1) << 4);
                uint32_t r0, r1, r2, r3;
                ldsm_x4(r0, r1, r2, r3, addr);
                b[np * 2][0] = r0; b[np * 2][1] = r1;
                b[np * 2 + 1][0] = r2; b[np * 2 + 1][1] = r3;
            }
            #pragma unroll
            for (int mf = 0; mf < 4; mf++)
                #pragma unroll
                for (int nf = 0; nf < 4; nf++)
                    mma16816(acc[mf][nf][0], acc[mf][nf][1], acc[mf][nf][2], acc[mf][nf][3],
                             a[mf][0], a[mf][1], a[mf][2], a[mf][3],
                             b[nf][0], b[nf][1]);
        }
    }

    #pragma unroll
    for (int mf = 0; mf < 4; mf++) {
        #pragma unroll
        for (int nf = 0; nf < 4; nf++) {
            int col = colBase + wn + nf * 8 + (lid & 3) * 2;
            #pragma unroll
            for (int h = 0; h < 2; h++) {
                int row = rowBase + wm + mf * 16 + (lid >> 2) + h * 8;
                #pragma unroll
                for (int e = 0; e < 2; e++) {
                    float v = acc[mf][nf][h * 2 + e] * alpha;
                    int cc = col + e;
                    if (EPI == 1) { v += bias[cc]; v = gelu_tanh(v); }
                    if (EPI == 2) { v += bias[cc] + add[(size_t)row * ldc + cc]; }
                    if (sizeof(CT) == 2)
                        *reinterpret_cast<__half*>(&C[(size_t)row * ldc + cc]) = __float2half(v);
                    else
                        *reinterpret_cast<float*>(&C[(size_t)row * ldc + cc]) = v;
                }
            }
        }
    }
}

// ================= hgemm256: 128x256 tile, warp 64x64, 3-stage ==================
// CAUSAL=1 (logits): tiles fully above the diagonal write 0 without computing
// (softmax adds -1e10 -> exp underflows to exactly 0 either way).
#define TA256 (128 * SROW)     // 10240
#define TB256 (256 * SROW)     // 20480
#define STG256 (TA256 + TB256) // 30720

template<int EPI, int CAUSAL, typename CT>
__global__ __launch_bounds__(256, 1)
void hgemm256(const __half* __restrict__ A, const __half* __restrict__ Bt,
              CT* __restrict__ C, const float* __restrict__ bias,
              const float* __restrict__ add,
              int K, int lda, int ldb, int ldc,
              long long sAb, long long sAh, long long sBb, long long sBh,
              long long sCb, long long sCh, int hdiv, float alpha) {
    extern __shared__ __align__(16) char smem[];       // 3 * STG256 = 92160 B
    const uint32_t sbase = smem_u32(smem);
    int tid = threadIdx.x, wid = tid >> 5, lid = tid & 31;

    int z = blockIdx.z, bb = z / hdiv, hh = z % hdiv;
    A  += bb * sAb + hh * sAh;
    Bt += bb * sBb + hh * sBh;
    C  += bb * sCb + hh * sCh;
    int rowBase = blockIdx.y * 128;
    int colBase = blockIdx.x * 256;

    int wm = (wid >> 2) * 64;       // 0/64
    int wn = (wid & 3) * 64;        // 0/64/128/192

    float acc[4][8][4];
    #pragma unroll
    for (int i = 0; i < 4; i++)
        #pragma unroll
        for (int j = 0; j < 8; j++)
            #pragma unroll
            for (int c = 0; c < 4; c++) acc[i][j][c] = 0.f;

    bool live = !(CAUSAL && (colBase > rowBase + 127));
    if (live) {
        const int NC = K >> 5;
        auto stage_load = [&](int st, int k0) {
            uint32_t base = sbase + st * STG256;
            #pragma unroll
            for (int l = 0; l < 6; l++) {
                int c = tid + l * 256;              // 0..1535
                if (c < 512) {
                    int r = c >> 2, kc = c & 3;
                    cp_async16(base + r * SROW + kc * 16,
                               A + (size_t)(rowBase + r) * lda + k0 + kc * 8);
                } else {
                    int u = c - 512;
                    int r = u >> 2, kc = u & 3;
                    cp_async16(base + TA256 + r * SROW + kc * 16,
                               Bt + (size_t)(colBase + r) * ldb + k0 + kc * 8);
                }
            }
            cp_commit();
        };

        stage_load(0, 0);
        stage_load(1, 32);

        for (int i = 0; i < NC; i++) {
            __syncthreads();                         // slot (i+2)%3 free (compute(i-1) done everywhere)
            if (i + 2 < NC)      { stage_load((i + 2) % 3, (i + 2) << 5); cp_wait<2>(); }
            else if (i + 1 < NC) { cp_wait<1>(); }
            else                 { cp_wait<0>(); }
            __syncthreads();                         // stage i visible to all

            uint32_t abase = sbase + (i % 3) * STG256;
            uint32_t bbase = abase + TA256;
            int which = lid >> 3, rim = lid & 7;

            #pragma unroll
            for (int ks = 0; ks < 2; ks++) {
                uint32_t a[4][4];
                #pragma unroll
                for (int mf = 0; mf < 4; mf++) {
                    int r = wm + mf * 16 + ((which & 1) << 3) + rim;
                    uint32_t addr = abase + r * SROW + ks * 32 + ((which >> 1) << 4);
                    ldsm_x4(a[mf][0], a[mf][1], a[mf][2], a[mf][3], addr);
                }
                uint32_t b[8][2];
                #pragma unroll
                for (int np = 0; np < 4; np++) {
                    int n = wn + np * 16 + ((which >> 1) << 3) + rim;
                    uint32_t addr = bbase + n * SROW + ks * 32 + ((which & 1) << 4);
                    uint32_t r0, r1, r2, r3;
                    ldsm_x4(r0, r1, r2, r3, addr);
                    b[np * 2][0] = r0; b[np * 2][1] = r1;
                    b[np * 2 + 1][0] = r2; b[np * 2 + 1][1] = r3;
                }
                #pragma unroll
                for (int mf = 0; mf < 4; mf++)
                    #pragma unroll
                    for (int nf = 0; nf < 8; nf++)
                        mma16816(acc[mf][nf][0], acc[mf][nf][1], acc[mf][nf][2], acc[mf][nf][3],
                                 a[mf][0], a[mf][1], a[mf][2], a[mf][3],
                                 b[nf][0], b[nf][1]);
            }
        }
    }

    #pragma unroll
    for (int mf = 0; mf < 4; mf++) {
        #pragma unroll
        for (int nf = 0; nf < 8; nf++) {
            int col = colBase + wn + nf * 8 + (lid & 3) * 2;
            #pragma unroll
            for (int h = 0; h < 2; h++) {
                int row = rowBase + wm + mf * 16 + (lid >> 2) + h * 8;
                #pragma unroll
                for (int e = 0; e < 2; e++) {
                    float v = acc[mf][nf][h * 2 + e] * alpha;
                    int cc = col + e;
                    if (EPI == 1) { v += bias[cc]; v = gelu_tanh(v); }
                    if (EPI == 2) { v += bias[cc] + add[(size_t)row * ldc + cc]; }
                    if (sizeof(CT) == 2)
                        *reinterpret_cast<__half*>(&C[(size_t)row * ldc + cc]) = __float2half(v);
                    else
                        *reinterpret_cast<float*>(&C[(size_t)row * ldc + cc]) = v;
                }
            }
        }
    }
}

// ---------------- launch --------------------------------------------------------
static void* symp(const void* s) { void* p = nullptr; cudaGetSymbolAddress(&p, s); return p; }

extern "C" void kernel_launch(void* const* d_in, const int* in_sizes, int n_in,
                              void* d_out, int out_size) {
    (void)in_sizes; (void)n_in; (void)out_size;
    const float* x         = (const float*)d_in[0];
    const float* attn_bias = (const float*)d_in[1];
    const float* ln_scale  = (const float*)d_in[2];
    const float* ln_offset = (const float*)d_in[3];
    const float* wq        = (const float*)d_in[4];
    const float* wk        = (const float*)d_in[5];
    const float* wv        = (const float*)d_in[6];
    const float* wo        = (const float*)d_in[7];
    const float* w_fc_in   = (const float*)d_in[8];
    const float* b_fc_in   = (const float*)d_in[9];
    const float* w_fc_out  = (const float*)d_in[10];
    const float* b_fc_out  = (const float*)d_in[11];
    float* out = (float*)d_out;

    __half* xn16  = (__half*)symp(g_xn16);
    float*  qkv   = (float*)symp(g_qkv);
    __half* q16   = (__half*)symp(g_q16);
    __half* k16   = (__half*)symp(g_k16);
    __half* v16t  = (__half*)symp(g_v16t);
    float*  lg    = (float*)symp(g_logits);
    __half* p16   = (__half*)symp(g_p16);
    __half* av16  = (__half*)symp(g_av16);
    float*  ao    = (float*)symp(g_ao);
    __half* h16   = (__half*)symp(g_h16);
    __half* wqkvt = (__half*)symp(g_wqkvt);
    __half* wot   = (__half*)symp(g_wot);
    __half* wfit  = (__half*)symp(g_wfit);
    __half* wfot  = (__half*)symp(g_wfot);

    const int SM3 = 3 * STG256;   // 92160
    cudaFuncSetAttribute(hgemm256<0, 0, float >, cudaFuncAttributeMaxDynamicSharedMemorySize, SM3);
    cudaFuncSetAttribute(hgemm256<0, 1, float >, cudaFuncAttributeMaxDynamicSharedMemorySize, SM3);
    cudaFuncSetAttribute(hgemm256<1, 0, __half>, cudaFuncAttributeMaxDynamicSharedMemorySize, SM3);
    cudaFuncSetAttribute(hgemm256<2, 0, float >, cudaFuncAttributeMaxDynamicSharedMemorySize, SM3);

    dim3 tb(32, 8), blk(256);

    sincos_kernel<<<(SEQ * HALFD + 255) / 256, 256>>>();
    // weight transposes -> fp16 K-major
    tconv_kernel<<<dim3(D_MODEL / 32, D_MODEL / 32), tb>>>(wq, wqkvt + 0 * (size_t)D_MODEL * D_MODEL, D_MODEL, D_MODEL);
    tconv_kernel<<<dim3(D_MODEL / 32, D_MODEL / 32), tb>>>(wk, wqkvt + 1 * (size_t)D_MODEL * D_MODEL, D_MODEL, D_MODEL);
    tconv_kernel<<<dim3(D_MODEL / 32, D_MODEL / 32), tb>>>(wv, wqkvt + 2 * (size_t)D_MODEL * D_MODEL, D_MODEL, D_MODEL);
    tconv_kernel<<<dim3(D_MODEL / 32, D_MODEL / 32), tb>>>(wo, wot, D_MODEL, D_MODEL);
    tconv_kernel<<<dim3(D_FF / 32, D_MODEL / 32), tb>>>(w_fc_in, wfit, D_MODEL, D_FF);
    tconv_kernel<<<dim3(D_MODEL / 32, D_FF / 32), tb>>>(w_fc_out, wfot, D_FF, D_MODEL);

    layernorm_kernel<<<MROWS, 256>>>(x, ln_scale, ln_offset);

    // fused QKV: z selects weight/output
    hgemm256<0, 0, float><<<dim3(D_MODEL / 256, MROWS / 128, 3), blk, SM3>>>(
        xn16, wqkvt, qkv, nullptr, nullptr,
        D_MODEL, D_MODEL, D_MODEL, D_MODEL,
        0, 0, (long long)D_MODEL * D_MODEL, 0, (long long)MROWS * D_MODEL, 0, 1, 1.f);

    rotary_kernel<<<(MROWS * N_HEADS * HALFD + 255) / 256, 256>>>(
        qkv, qkv + (size_t)MROWS * D_MODEL);
    vtrans_kernel<<<dim3(SEQ / 32, DPH / 32, BH), tb>>>(qkv + 2 * (size_t)MROWS * D_MODEL);

    // logits[bh] = q16 @ k16^T / sqrt(dph); fully-masked tiles skipped
    hgemm256<0, 1, float><<<dim3(SEQ / 256, SEQ / 128, BH), blk, SM3>>>(
        q16, k16, lg, nullptr, nullptr,
        DPH, D_MODEL, D_MODEL, SEQ,
        (long long)SEQ * D_MODEL, (long long)DPH,
        (long long)SEQ * D_MODEL, (long long)DPH,
        (long long)N_HEADS * SEQ * SEQ, (long long)SEQ * SEQ,
        N_HEADS, 0.08838834764831845f);

    softmax_kernel<<<BH * SEQ, 256>>>(attn_bias);

    // attn_vec[bh] = P @ V, causal K-clamp (exact)
    hgemm<0, 1, __half><<<dim3(DPH / 128, SEQ / 128, BH), blk>>>(
        p16, v16t, av16, nullptr, nullptr,
        SEQ, SEQ, SEQ, D_MODEL,
        (long long)N_HEADS * SEQ * SEQ, (long long)SEQ * SEQ,
        (long long)N_HEADS * DPH * SEQ, (long long)DPH * SEQ,
        (long long)SEQ * D_MODEL, (long long)DPH,
        N_HEADS, 1.f);

    // attn_out = attn_vec @ wo
    hgemm256<0, 0, float><<<dim3(D_MODEL / 256, MROWS / 128, 1), blk, SM3>>>(
        av16, wot, ao, nullptr, nullptr,
        D_MODEL, D_MODEL, D_MODEL, D_MODEL,
        0, 0, 0, 0, 0, 0, 1, 1.f);

    // h = gelu(xn @ w_fc_in + b_fc_in)  -> fp16
    hgemm256<1, 0, __half><<<dim3(D_FF / 256, MROWS / 128, 1), blk, SM3>>>(
        xn16, wfit, h16, b_fc_in, nullptr,
        D_MODEL, D_MODEL, D_MODEL, D_FF,
        0, 0, 0, 0, 0, 0, 1, 1.f);

    // out = h @ w_fc_out + b_fc_out + attn_out
    hgemm256<2, 0, float><<<dim3(D_MODEL / 256, MROWS / 128, 1), blk, SM3>>>(
        h16, wfot, out, b_fc_out, ao,
        D_FF, D_FF, D_FF, D_MODEL,
        0, 0, 0, 0, 0, 0, 1, 1.f);
}

// round 10
// speedup vs baseline: 1.1341x; 1.1341x over previous
#include <cuda_runtime.h>
#include <cuda_fp16.h>
#include <math.h>
#include <stdint.h>

#define D_MODEL 2048
#define N_HEADS 16
#define DPH     128
#define D_FF    8192
#define BATCH   2
#define SEQ     2048
#define MROWS   (BATCH*SEQ)
#define HALFD   (DPH/2)
#define BH      (BATCH*N_HEADS)

// ---------------- scratch (static device arrays; no cudaMalloc) ----------------
// NOTE: g_logits is zero-initialized at module load; fully-masked logit tiles are
// never written by any kernel, so softmax reads exact 0 there (see causal skip).
__device__ __half g_xn16[(size_t)MROWS*D_MODEL];
__device__ float  g_qkv [(size_t)3*MROWS*D_MODEL];
__device__ __half g_q16 [(size_t)MROWS*D_MODEL];
__device__ __half g_k16 [(size_t)MROWS*D_MODEL];
__device__ __half g_v16t[(size_t)BH*DPH*SEQ];
__device__ float  g_logits[(size_t)BH*SEQ*SEQ];
__device__ __half g_p16 [(size_t)BH*SEQ*SEQ];
__device__ __half g_av16[(size_t)MROWS*D_MODEL];
__device__ float  g_ao  [(size_t)MROWS*D_MODEL];
__device__ __half g_h16 [(size_t)MROWS*D_FF];
__device__ __half g_wqkvt[(size_t)3*D_MODEL*D_MODEL];
__device__ __half g_wot [(size_t)D_MODEL*D_MODEL];
__device__ __half g_wfit[(size_t)D_FF*D_MODEL];
__device__ __half g_wfot[(size_t)D_MODEL*D_FF];
__device__ float2 g_sincos[(size_t)SEQ*HALFD];

// ---------------- family-portable PTX helpers -----------------------------------
__device__ __forceinline__ uint32_t smem_u32(const void* p) {
    uint32_t a;
    asm("{ .reg .u64 t; cvta.to.shared.u64 t, %1; cvt.u32.u64 %0, t; }" : "=r"(a) : "l"(p));
    return a;
}
__device__ __forceinline__ void cp_async16(uint32_t saddr, const void* gptr) {
    asm volatile("cp.async.cg.shared.global [%0], [%1], 16;" :: "r"(saddr), "l"(gptr));
}
__device__ __forceinline__ void cp_commit() {
    asm volatile("cp.async.commit_group;" ::: "memory");
}
template<int N>
__device__ __forceinline__ void cp_wait() {
    asm volatile("cp.async.wait_group %0;" :: "n"(N) : "memory");
}
__device__ __forceinline__ void ldsm_x4(uint32_t& r0, uint32_t& r1, uint32_t& r2, uint32_t& r3,
                                        uint32_t addr) {
    asm volatile("ldmatrix.sync.aligned.m8n8.x4.shared.b16 {%0,%1,%2,%3}, [%4];"
        : "=r"(r0), "=r"(r1), "=r"(r2), "=r"(r3) : "r"(addr));
}
__device__ __forceinline__ void mma16816(float& c0, float& c1, float& c2, float& c3,
                                         uint32_t a0, uint32_t a1, uint32_t a2, uint32_t a3,
                                         uint32_t b0, uint32_t b1) {
    asm volatile("mma.sync.aligned.m16n8k16.row.col.f32.f16.f16.f32 "
        "{%0,%1,%2,%3}, {%4,%5,%6,%7}, {%8,%9}, {%0,%1,%2,%3};"
        : "+f"(c0), "+f"(c1), "+f"(c2), "+f"(c3)
        : "r"(a0), "r"(a1), "r"(a2), "r"(a3), "r"(b0), "r"(b1));
}

// ---------------- small kernels -------------------------------------------------
__global__ void sincos_kernel() {
    int idx = blockIdx.x * blockDim.x + threadIdx.x;
    if (idx >= SEQ * HALFD) return;
    int t = idx / HALFD, i = idx % HALFD;
    double invf = pow(10000.0, -(2.0 * i) / (double)DPH);
    double ang  = (double)t * invf;
    g_sincos[idx] = make_float2((float)sin(ang), (float)cos(ang));
}

__global__ void layernorm_kernel(const float* __restrict__ x,
                                 const float* __restrict__ scale,
                                 const float* __restrict__ offset) {
    int row = blockIdx.x;
    const float* xr = x + (size_t)row * D_MODEL;
    __half* o = g_xn16 + (size_t)row * D_MODEL;
    float s = 0.f, s2 = 0.f;
    for (int j = threadIdx.x; j < D_MODEL; j += blockDim.x) {
        float v = xr[j]; s += v; s2 += v * v;
    }
    __shared__ float red[64];
    #pragma unroll
    for (int off = 16; off; off >>= 1) {
        s  += __shfl_xor_sync(0xffffffffu, s,  off);
        s2 += __shfl_xor_sync(0xffffffffu, s2, off);
    }
    int wid = threadIdx.x >> 5, lid = threadIdx.x & 31;
    if (lid == 0) { red[wid] = s; red[wid + 32] = s2; }
    __syncthreads();
    if (threadIdx.x < 32) {
        int nw = blockDim.x >> 5;
        s  = (threadIdx.x < nw) ? red[threadIdx.x]      : 0.f;
        s2 = (threadIdx.x < nw) ? red[threadIdx.x + 32] : 0.f;
        #pragma unroll
        for (int off = 16; off; off >>= 1) {
            s  += __shfl_xor_sync(0xffffffffu, s,  off);
            s2 += __shfl_xor_sync(0xffffffffu, s2, off);
        }
        if (lid == 0) { red[0] = s; red[1] = s2; }
    }
    __syncthreads();
    float mean = red[0] / D_MODEL;
    float var  = red[1] / D_MODEL - mean * mean;
    float r    = rsqrtf(var + 1e-5f);
    for (int j = threadIdx.x; j < D_MODEL; j += blockDim.x)
        o[j] = __float2half(scale[j] * r * (xr[j] - mean) + offset[j]);
}

// rotary: fp32 q/k -> fp16 q16/k16
__global__ void rotary_kernel(const float* __restrict__ q, const float* __restrict__ k) {
    int idx = blockIdx.x * blockDim.x + threadIdx.x;
    if (idx >= MROWS * N_HEADS * HALFD) return;
    int half = idx % HALFD;
    int rest = idx / HALFD;
    int h    = rest % N_HEADS;
    int row  = rest / N_HEADS;
    int t    = row % SEQ;
    float2 sc = g_sincos[t * HALFD + half];
    size_t base = (size_t)row * D_MODEL + h * DPH + 2 * half;
    float q0 = q[base], q1 = q[base + 1];
    g_q16[base]     = __float2half(q0 * sc.y - q1 * sc.x);
    g_q16[base + 1] = __float2half(q1 * sc.y + q0 * sc.x);
    float k0 = k[base], k1 = k[base + 1];
    g_k16[base]     = __float2half(k0 * sc.y - k1 * sc.x);
    g_k16[base + 1] = __float2half(k1 * sc.y + k0 * sc.x);
}

// weight transpose+convert: in[R][C] fp32 -> out[C][R] fp16
__global__ void tconv_kernel(const float* __restrict__ in, __half* __restrict__ out,
                             int R, int C) {
    __shared__ float t[32][33];
    int bx = blockIdx.x * 32, by = blockIdx.y * 32;
    int tx = threadIdx.x, ty = threadIdx.y;
    #pragma unroll
    for (int i = 0; i < 4; i++)
        t[ty + i * 8][tx] = in[(size_t)(by + ty + i * 8) * C + bx + tx];
    __syncthreads();
    #pragma unroll
    for (int i = 0; i < 4; i++)
        out[(size_t)(bx + ty + i * 8) * R + by + tx] = __float2half(t[tx][ty + i * 8]);
}

// V transpose: fp32 [b*S+t][h*128+d] -> v16t [bh][d][t] fp16
__global__ void vtrans_kernel(const float* __restrict__ v) {
    __shared__ float t[32][33];
    int z = blockIdx.z, bb = z >> 4, hh = z & 15;
    int tb = blockIdx.x * 32, db = blockIdx.y * 32;
    int tx = threadIdx.x, ty = threadIdx.y;
    #pragma unroll
    for (int i = 0; i < 4; i++)
        t[ty + i * 8][tx] = v[(size_t)(bb * SEQ + tb + ty + i * 8) * D_MODEL + hh * DPH + db + tx];
    __syncthreads();
    #pragma unroll
    for (int i = 0; i < 4; i++)
        g_v16t[((size_t)z * DPH + db + ty + i * 8) * SEQ + tb + tx] = __float2half(t[tx][ty + i * 8]);
}

__device__ __forceinline__ float gelu_tanh(float x) {
    float x3 = x * x * x;
    float t = tanhf(0.7978845608028654f * (x + 0.044715f * x3));
    return 0.5f * x * (1.f + t);
}

// masked softmax: fp32 logits (+bias, causal) -> fp16 probs
// chunks fully beyond the diagonal are skipped (exp(-1e10) == 0 in fp32: exact)
__global__ __launch_bounds__(256)
void softmax_kernel(const float* __restrict__ attn_bias) {
    long long r = blockIdx.x;
    int i = (int)(r % SEQ);
    const float* row = g_logits + r * SEQ;
    __half* prow = g_p16 + r * SEQ;
    const float* brow = attn_bias + (size_t)i * SEQ;
    int tid = threadIdx.x;
    float vals[8];
    float mx = -INFINITY;
    #pragma unroll
    for (int l = 0; l < 8; l++) {
        int j = tid + l * 256;
        float v;
        if (l * 256 <= i) {                 // uniform per block: no divergence
            v = row[j] + brow[j];
            if (j > i) v += -1e10f;
        } else {
            v = -1e30f;                     // exp -> exactly 0
        }
        vals[l] = v;
        mx = fmaxf(mx, v);
    }
    __shared__ float red[32];
    #pragma unroll
    for (int off = 16; off; off >>= 1)
        mx = fmaxf(mx, __shfl_xor_sync(0xffffffffu, mx, off));
    int wid = tid >> 5, lid = tid & 31;
    if (lid == 0) red[wid] = mx;
    __syncthreads();
    if (tid < 32) {
        mx = (tid < 8) ? red[tid] : -INFINITY;
        #pragma unroll
        for (int off = 4; off; off >>= 1)
            mx = fmaxf(mx, __shfl_xor_sync(0xffffffffu, mx, off));
        if (lid == 0) red[0] = mx;
    }
    __syncthreads();
    mx = red[0];
    float sum = 0.f;
    #pragma unroll
    for (int l = 0; l < 8; l++) { vals[l] = expf(vals[l] - mx); sum += vals[l]; }
    #pragma unroll
    for (int off = 16; off; off >>= 1)
        sum += __shfl_xor_sync(0xffffffffu, sum, off);
    if (lid == 0) red[wid] = sum;
    __syncthreads();
    if (tid < 32) {
        sum = (tid < 8) ? red[tid] : 0.f;
        #pragma unroll
        for (int off = 4; off; off >>= 1)
            sum += __shfl_xor_sync(0xffffffffu, sum, off);
        if (lid == 0) red[0] = sum;
    }
    __syncthreads();
    float inv = 1.f / red[0];
    #pragma unroll
    for (int l = 0; l < 8; l++)
        prow[tid + l * 256] = __float2half(vals[l] * inv);
}

// ---------------- mma.sync fp16 GEMM (round-7 proven 128x128 engine) -------------
// C[M,N] = alpha * A[M,K] @ Bt[N,K]^T (+ epilogue). A, Bt K-major fp16.
// CTA 128x128x32, 256 threads = 8 warps (2m x 4n), warp tile 64x32, 2-stage.
// EPI: 0 plain, 1 bias+gelu, 2 bias+add
// CKLAMP (PV): K clamped to rowBase+128 (P[r][c]==0 for c>r) - exact.
// CSKIP (logits): tiles fully above the diagonal return immediately; their
//   g_logits entries remain 0 (zero-init, never written) and softmax's -1e10
//   makes exp exactly 0 - exact.
#define SROW   80              // bytes per padded smem row (64B payload, 20-bank stride)
#define TILE_B (128 * SROW)
#define STAGE_B (2 * TILE_B)

template<int EPI, int CKLAMP, int CSKIP, typename CT>
__global__ __launch_bounds__(256)
void hgemm(const __half* __restrict__ A, const __half* __restrict__ Bt,
           CT* __restrict__ C, const float* __restrict__ bias,
           const float* __restrict__ add,
           int K, int lda, int ldb, int ldc,
           long long sAb, long long sAh, long long sBb, long long sBh,
           long long sCb, long long sCh, int hdiv, float alpha) {
    __shared__ __align__(16) char smem[2 * STAGE_B];   // 40 KB
    const uint32_t sbase = smem_u32(smem);
    int tid = threadIdx.x, wid = tid >> 5, lid = tid & 31;

    int rowBase = blockIdx.y * 128;
    int colBase = blockIdx.x * 128;
    if (CSKIP && colBase > rowBase + 127) return;   // fully-masked logit tile

    int z = blockIdx.z, bb = z / hdiv, hh = z % hdiv;
    A  += bb * sAb + hh * sAh;
    Bt += bb * sBb + hh * sBh;
    C  += bb * sCb + hh * sCh;

    int wm = (wid >> 2) * 64;
    int wn = (wid & 3) * 32;

    float acc[4][4][4];
    #pragma unroll
    for (int i = 0; i < 4; i++)
        #pragma unroll
        for (int j = 0; j < 4; j++)
            #pragma unroll
            for (int c = 0; c < 4; c++) acc[i][j][c] = 0.f;

    int Keff = CKLAMP ? min(K, rowBase + 128) : K;
    const int NC = Keff >> 5;
    auto stage_load = [&](int st, int k0) {
        uint32_t base = sbase + st * STAGE_B;
        #pragma unroll
        for (int l = 0; l < 4; l++) {
            int c = tid + l * 256;
            int r  = (c & 511) >> 2;
            int kc = c & 3;
            if (c < 512)
                cp_async16(base + r * SROW + kc * 16,
                           A + (size_t)(rowBase + r) * lda + k0 + kc * 8);
            else
                cp_async16(base + TILE_B + r * SROW + kc * 16,
                           Bt + (size_t)(colBase + r) * ldb + k0 + kc * 8);
        }
        cp_commit();
    };

    stage_load(0, 0);

    for (int i = 0; i < NC; i++) {
        __syncthreads();
        if (i + 1 < NC) { stage_load((i + 1) & 1, (i + 1) << 5); cp_wait<1>(); }
        else            { cp_wait<0>(); }
        __syncthreads();

        uint32_t abase = sbase + (i & 1) * STAGE_B;
        uint32_t bbase = abase + TILE_B;
        int which = lid >> 3, rim = lid & 7;

        #pragma unroll
        for (int ks = 0; ks < 2; ks++) {
            uint32_t a[4][4];
            #pragma unroll
            for (int mf = 0; mf < 4; mf++) {
                int r = wm + mf * 16 + ((which & 1) << 3) + rim;
                uint32_t addr = abase + r * SROW + ks * 32 + ((which >> 1) << 4);
                ldsm_x4(a[mf][0], a[mf][1], a[mf][2], a[mf][3], addr);
            }
            uint32_t b[4][2];
            #pragma unroll
            for (int np = 0; np < 2; np++) {
                int n = wn + np * 16 + ((which >> 1) << 3) + rim;
                uint32_t addr = bbase + n * SROW + ks * 32 + ((which & 1) << 4);
                uint32_t r0, r1, r2, r3;
                ldsm_x4(r0, r1, r2, r3, addr);
                b[np * 2][0] = r0; b[np * 2][1] = r1;
                b[np * 2 + 1][0] = r2; b[np * 2 + 1][1] = r3;
            }
            #pragma unroll
            for (int mf = 0; mf < 4; mf++)
                #pragma unroll
                for (int nf = 0; nf < 4; nf++)
                    mma16816(acc[mf][nf][0], acc[mf][nf][1], acc[mf][nf][2], acc[mf][nf][3],
                             a[mf][0], a[mf][1], a[mf][2], a[mf][3],
                             b[nf][0], b[nf][1]);
        }
    }

    // epilogue: fragment -> gmem (c0,c1 at row lid/4; c2,c3 at row lid/4+8)
    #pragma unroll
    for (int mf = 0; mf < 4; mf++) {
        #pragma unroll
        for (int nf = 0; nf < 4; nf++) {
            int col = colBase + wn + nf * 8 + (lid & 3) * 2;
            #pragma unroll
            for (int h = 0; h < 2; h++) {
                int row = rowBase + wm + mf * 16 + (lid >> 2) + h * 8;
                #pragma unroll
                for (int e = 0; e < 2; e++) {
                    float v = acc[mf][nf][h * 2 + e] * alpha;
                    int cc = col + e;
                    if (EPI == 1) { v += bias[cc]; v = gelu_tanh(v); }
                    if (EPI == 2) { v += bias[cc] + add[(size_t)row * ldc + cc]; }
                    if (sizeof(CT) == 2)
                        *reinterpret_cast<__half*>(&C[(size_t)row * ldc + cc]) = __float2half(v);
                    else
                        *reinterpret_cast<float*>(&C[(size_t)row * ldc + cc]) = v;
                }
            }
        }
    }
}

// ---------------- launch --------------------------------------------------------
static void* symp(const void* s) { void* p = nullptr; cudaGetSymbolAddress(&p, s); return p; }

extern "C" void kernel_launch(void* const* d_in, const int* in_sizes, int n_in,
                              void* d_out, int out_size) {
    (void)in_sizes; (void)n_in; (void)out_size;
    const float* x         = (const float*)d_in[0];
    const float* attn_bias = (const float*)d_in[1];
    const float* ln_scale  = (const float*)d_in[2];
    const float* ln_offset = (const float*)d_in[3];
    const float* wq        = (const float*)d_in[4];
    const float* wk        = (const float*)d_in[5];
    const float* wv        = (const float*)d_in[6];
    const float* wo        = (const float*)d_in[7];
    const float* w_fc_in   = (const float*)d_in[8];
    const float* b_fc_in   = (const float*)d_in[9];
    const float* w_fc_out  = (const float*)d_in[10];
    const float* b_fc_out  = (const float*)d_in[11];
    float* out = (float*)d_out;

    __half* xn16  = (__half*)symp(g_xn16);
    float*  qkv   = (float*)symp(g_qkv);
    __half* q16   = (__half*)symp(g_q16);
    __half* k16   = (__half*)symp(g_k16);
    __half* v16t  = (__half*)symp(g_v16t);
    float*  lg    = (float*)symp(g_logits);
    __half* p16   = (__half*)symp(g_p16);
    __half* av16  = (__half*)symp(g_av16);
    float*  ao    = (float*)symp(g_ao);
    __half* h16   = (__half*)symp(g_h16);
    __half* wqkvt = (__half*)symp(g_wqkvt);
    __half* wot   = (__half*)symp(g_wot);
    __half* wfit  = (__half*)symp(g_wfit);
    __half* wfot  = (__half*)symp(g_wfot);

    dim3 tb(32, 8), blk(256);

    sincos_kernel<<<(SEQ * HALFD + 255) / 256, 256>>>();
    // weight transposes -> fp16 K-major
    tconv_kernel<<<dim3(D_MODEL / 32, D_MODEL / 32), tb>>>(wq, wqkvt + 0 * (size_t)D_MODEL * D_MODEL, D_MODEL, D_MODEL);
    tconv_kernel<<<dim3(D_MODEL / 32, D_MODEL / 32), tb>>>(wk, wqkvt + 1 * (size_t)D_MODEL * D_MODEL, D_MODEL, D_MODEL);
    tconv_kernel<<<dim3(D_MODEL / 32, D_MODEL / 32), tb>>>(wv, wqkvt + 2 * (size_t)D_MODEL * D_MODEL, D_MODEL, D_MODEL);
    tconv_kernel<<<dim3(D_MODEL / 32, D_MODEL / 32), tb>>>(wo, wot, D_MODEL, D_MODEL);
    tconv_kernel<<<dim3(D_FF / 32, D_MODEL / 32), tb>>>(w_fc_in, wfit, D_MODEL, D_FF);
    tconv_kernel<<<dim3(D_MODEL / 32, D_FF / 32), tb>>>(w_fc_out, wfot, D_FF, D_MODEL);

    layernorm_kernel<<<MROWS, 256>>>(x, ln_scale, ln_offset);

    // fused QKV: z selects weight/output
    hgemm<0, 0, 0, float><<<dim3(D_MODEL / 128, MROWS / 128, 3), blk>>>(
        xn16, wqkvt, qkv, nullptr, nullptr,
        D_MODEL, D_MODEL, D_MODEL, D_MODEL,
        0, 0, (long long)D_MODEL * D_MODEL, 0, (long long)MROWS * D_MODEL, 0, 1, 1.f);

    rotary_kernel<<<(MROWS * N_HEADS * HALFD + 255) / 256, 256>>>(
        qkv, qkv + (size_t)MROWS * D_MODEL);
    vtrans_kernel<<<dim3(SEQ / 32, DPH / 32, BH), tb>>>(qkv + 2 * (size_t)MROWS * D_MODEL);

    // logits[bh] = q16 @ k16^T / sqrt(dph); fully-masked tiles early-return
    hgemm<0, 0, 1, float><<<dim3(SEQ / 128, SEQ / 128, BH), blk>>>(
        q16, k16, lg, nullptr, nullptr,
        DPH, D_MODEL, D_MODEL, SEQ,
        (long long)SEQ * D_MODEL, (long long)DPH,
        (long long)SEQ * D_MODEL, (long long)DPH,
        (long long)N_HEADS * SEQ * SEQ, (long long)SEQ * SEQ,
        N_HEADS, 0.08838834764831845f);

    softmax_kernel<<<BH * SEQ, 256>>>(attn_bias);

    // attn_vec[bh] = P @ V, causal K-clamp (exact)
    hgemm<0, 1, 0, __half><<<dim3(DPH / 128, SEQ / 128, BH), blk>>>(
        p16, v16t, av16, nullptr, nullptr,
        SEQ, SEQ, SEQ, D_MODEL,
        (long long)N_HEADS * SEQ * SEQ, (long long)SEQ * SEQ,
        (long long)N_HEADS * DPH * SEQ, (long long)DPH * SEQ,
        (long long)SEQ * D_MODEL, (long long)DPH,
        N_HEADS, 1.f);

    // attn_out = attn_vec @ wo
    hgemm<0, 0, 0, float><<<dim3(D_MODEL / 128, MROWS / 128, 1), blk>>>(
        av16, wot, ao, nullptr, nullptr,
        D_MODEL, D_MODEL, D_MODEL, D_MODEL,
        0, 0, 0, 0, 0, 0, 1, 1.f);

    // h = gelu(xn @ w_fc_in + b_fc_in)  -> fp16
    hgemm<1, 0, 0, __half><<<dim3(D_FF / 128, MROWS / 128, 1), blk>>>(
        xn16, wfit, h16, b_fc_in, nullptr,
        D_MODEL, D_MODEL, D_MODEL, D_FF,
        0, 0, 0, 0, 0, 0, 1, 1.f);

    // out = h @ w_fc_out + b_fc_out + attn_out
    hgemm<2, 0, 0, float><<<dim3(D_MODEL / 128, MROWS / 128, 1), blk>>>(
        h16, wfot, out, b_fc_out, ao,
        D_FF, D_FF, D_FF, D_MODEL,
        0, 0, 0, 0, 0, 0, 1, 1.f);
}

// round 16
// speedup vs baseline: 1.2168x; 1.0729x over previous
#include <cuda_runtime.h>
#include <cuda_fp16.h>
#include <math.h>
#include <stdint.h>

#define D_MODEL 2048
#define N_HEADS 16
#define DPH     128
#define D_FF    8192
#define BATCH   2
#define SEQ     2048
#define MROWS   (BATCH*SEQ)
#define HALFD   (DPH/2)
#define BH      (BATCH*N_HEADS)

// ---------------- scratch (static device arrays; no cudaMalloc) ----------------
// NOTE: g_logits is zero-initialized at module load; fully-masked logit tiles are
// never written by any kernel, so softmax reads exact 0 there (see causal skip).
__device__ __half g_xn16[(size_t)MROWS*D_MODEL];
__device__ float  g_qkv [(size_t)3*MROWS*D_MODEL];
__device__ __half g_q16 [(size_t)MROWS*D_MODEL];
__device__ __half g_k16 [(size_t)MROWS*D_MODEL];
__device__ __half g_v16t[(size_t)BH*DPH*SEQ];
__device__ float  g_logits[(size_t)BH*SEQ*SEQ];
__device__ __half g_p16 [(size_t)BH*SEQ*SEQ];
__device__ __half g_av16[(size_t)MROWS*D_MODEL];
__device__ float  g_ao  [(size_t)MROWS*D_MODEL];
__device__ __half g_h16 [(size_t)MROWS*D_FF];
__device__ __half g_wqkvt[(size_t)3*D_MODEL*D_MODEL];
__device__ __half g_wot [(size_t)D_MODEL*D_MODEL];
__device__ __half g_wfit[(size_t)D_FF*D_MODEL];
__device__ __half g_wfot[(size_t)D_MODEL*D_FF];
__device__ float2 g_sincos[(size_t)SEQ*HALFD];

// ---------------- family-portable PTX helpers -----------------------------------
__device__ __forceinline__ uint32_t smem_u32(const void* p) {
    uint32_t a;
    asm("{ .reg .u64 t; cvta.to.shared.u64 t, %1; cvt.u32.u64 %0, t; }" : "=r"(a) : "l"(p));
    return a;
}
__device__ __forceinline__ void cp_async16(uint32_t saddr, const void* gptr) {
    asm volatile("cp.async.cg.shared.global [%0], [%1], 16;" :: "r"(saddr), "l"(gptr));
}
__device__ __forceinline__ void cp_commit() {
    asm volatile("cp.async.commit_group;" ::: "memory");
}
template<int N>
__device__ __forceinline__ void cp_wait() {
    asm volatile("cp.async.wait_group %0;" :: "n"(N) : "memory");
}
__device__ __forceinline__ void ldsm_x4(uint32_t& r0, uint32_t& r1, uint32_t& r2, uint32_t& r3,
                                        uint32_t addr) {
    asm volatile("ldmatrix.sync.aligned.m8n8.x4.shared.b16 {%0,%1,%2,%3}, [%4];"
        : "=r"(r0), "=r"(r1), "=r"(r2), "=r"(r3) : "r"(addr));
}
__device__ __forceinline__ void mma16816(float& c0, float& c1, float& c2, float& c3,
                                         uint32_t a0, uint32_t a1, uint32_t a2, uint32_t a3,
                                         uint32_t b0, uint32_t b1) {
    asm volatile("mma.sync.aligned.m16n8k16.row.col.f32.f16.f16.f32 "
        "{%0,%1,%2,%3}, {%4,%5,%6,%7}, {%8,%9}, {%0,%1,%2,%3};"
        : "+f"(c0), "+f"(c1), "+f"(c2), "+f"(c3)
        : "r"(a0), "r"(a1), "r"(a2), "r"(a3), "r"(b0), "r"(b1));
}

// ---------------- small kernels -------------------------------------------------
__global__ void sincos_kernel() {
    int idx = blockIdx.x * blockDim.x + threadIdx.x;
    if (idx >= SEQ * HALFD) return;
    int t = idx / HALFD, i = idx % HALFD;
    double invf = pow(10000.0, -(2.0 * i) / (double)DPH);
    double ang  = (double)t * invf;
    g_sincos[idx] = make_float2((float)sin(ang), (float)cos(ang));
}

__global__ void layernorm_kernel(const float* __restrict__ x,
                                 const float* __restrict__ scale,
                                 const float* __restrict__ offset) {
    int row = blockIdx.x;
    const float* xr = x + (size_t)row * D_MODEL;
    __half* o = g_xn16 + (size_t)row * D_MODEL;
    float s = 0.f, s2 = 0.f;
    for (int j = threadIdx.x; j < D_MODEL; j += blockDim.x) {
        float v = xr[j]; s += v; s2 += v * v;
    }
    __shared__ float red[64];
    #pragma unroll
    for (int off = 16; off; off >>= 1) {
        s  += __shfl_xor_sync(0xffffffffu, s,  off);
        s2 += __shfl_xor_sync(0xffffffffu, s2, off);
    }
    int wid = threadIdx.x >> 5, lid = threadIdx.x & 31;
    if (lid == 0) { red[wid] = s; red[wid + 32] = s2; }
    __syncthreads();
    if (threadIdx.x < 32) {
        int nw = blockDim.x >> 5;
        s  = (threadIdx.x < nw) ? red[threadIdx.x]      : 0.f;
        s2 = (threadIdx.x < nw) ? red[threadIdx.x + 32] : 0.f;
        #pragma unroll
        for (int off = 16; off; off >>= 1) {
            s  += __shfl_xor_sync(0xffffffffu, s,  off);
            s2 += __shfl_xor_sync(0xffffffffu, s2, off);
        }
        if (lid == 0) { red[0] = s; red[1] = s2; }
    }
    __syncthreads();
    float mean = red[0] / D_MODEL;
    float var  = red[1] / D_MODEL - mean * mean;
    float r    = rsqrtf(var + 1e-5f);
    for (int j = threadIdx.x; j < D_MODEL; j += blockDim.x)
        o[j] = __float2half(scale[j] * r * (xr[j] - mean) + offset[j]);
}

// rotary: fp32 q/k -> fp16 q16/k16
__global__ void rotary_kernel(const float* __restrict__ q, const float* __restrict__ k) {
    int idx = blockIdx.x * blockDim.x + threadIdx.x;
    if (idx >= MROWS * N_HEADS * HALFD) return;
    int half = idx % HALFD;
    int rest = idx / HALFD;
    int h    = rest % N_HEADS;
    int row  = rest / N_HEADS;
    int t    = row % SEQ;
    float2 sc = g_sincos[t * HALFD + half];
    size_t base = (size_t)row * D_MODEL + h * DPH + 2 * half;
    float q0 = q[base], q1 = q[base + 1];
    g_q16[base]     = __float2half(q0 * sc.y - q1 * sc.x);
    g_q16[base + 1] = __float2half(q1 * sc.y + q0 * sc.x);
    float k0 = k[base], k1 = k[base + 1];
    g_k16[base]     = __float2half(k0 * sc.y - k1 * sc.x);
    g_k16[base + 1] = __float2half(k1 * sc.y + k0 * sc.x);
}

// weight transpose+convert: in[R][C] fp32 -> out[C][R] fp16
__global__ void tconv_kernel(const float* __restrict__ in, __half* __restrict__ out,
                             int R, int C) {
    __shared__ float t[32][33];
    int bx = blockIdx.x * 32, by = blockIdx.y * 32;
    int tx = threadIdx.x, ty = threadIdx.y;
    #pragma unroll
    for (int i = 0; i < 4; i++)
        t[ty + i * 8][tx] = in[(size_t)(by + ty + i * 8) * C + bx + tx];
    __syncthreads();
    #pragma unroll
    for (int i = 0; i < 4; i++)
        out[(size_t)(bx + ty + i * 8) * R + by + tx] = __float2half(t[tx][ty + i * 8]);
}

// V transpose: fp32 [b*S+t][h*128+d] -> v16t [bh][d][t] fp16
__global__ void vtrans_kernel(const float* __restrict__ v) {
    __shared__ float t[32][33];
    int z = blockIdx.z, bb = z >> 4, hh = z & 15;
    int tb = blockIdx.x * 32, db = blockIdx.y * 32;
    int tx = threadIdx.x, ty = threadIdx.y;
    #pragma unroll
    for (int i = 0; i < 4; i++)
        t[ty + i * 8][tx] = v[(size_t)(bb * SEQ + tb + ty + i * 8) * D_MODEL + hh * DPH + db + tx];
    __syncthreads();
    #pragma unroll
    for (int i = 0; i < 4; i++)
        g_v16t[((size_t)z * DPH + db + ty + i * 8) * SEQ + tb + tx] = __float2half(t[tx][ty + i * 8]);
}

__device__ __forceinline__ float gelu_tanh(float x) {
    float x3 = x * x * x;
    float t = tanhf(0.7978845608028654f * (x + 0.044715f * x3));
    return 0.5f * x * (1.f + t);
}

// masked softmax: fp32 logits (+bias, causal) -> fp16 probs
// chunks fully beyond the diagonal are skipped (exp(-1e10) == 0 in fp32: exact)
__global__ __launch_bounds__(256)
void softmax_kernel(const float* __restrict__ attn_bias) {
    long long r = blockIdx.x;
    int i = (int)(r % SEQ);
    const float* row = g_logits + r * SEQ;
    __half* prow = g_p16 + r * SEQ;
    const float* brow = attn_bias + (size_t)i * SEQ;
    int tid = threadIdx.x;
    float vals[8];
    float mx = -INFINITY;
    #pragma unroll
    for (int l = 0; l < 8; l++) {
        int j = tid + l * 256;
        float v;
        if (l * 256 <= i) {                 // uniform per block: no divergence
            v = row[j] + brow[j];
            if (j > i) v += -1e10f;
        } else {
            v = -1e30f;                     // exp -> exactly 0
        }
        vals[l] = v;
        mx = fmaxf(mx, v);
    }
    __shared__ float red[32];
    #pragma unroll
    for (int off = 16; off; off >>= 1)
        mx = fmaxf(mx, __shfl_xor_sync(0xffffffffu, mx, off));
    int wid = tid >> 5, lid = tid & 31;
    if (lid == 0) red[wid] = mx;
    __syncthreads();
    if (tid < 32) {
        mx = (tid < 8) ? red[tid] : -INFINITY;
        #pragma unroll
        for (int off = 4; off; off >>= 1)
            mx = fmaxf(mx, __shfl_xor_sync(0xffffffffu, mx, off));
        if (lid == 0) red[0] = mx;
    }
    __syncthreads();
    mx = red[0];
    float sum = 0.f;
    #pragma unroll
    for (int l = 0; l < 8; l++) { vals[l] = expf(vals[l] - mx); sum += vals[l]; }
    #pragma unroll
    for (int off = 16; off; off >>= 1)
        sum += __shfl_xor_sync(0xffffffffu, sum, off);
    if (lid == 0) red[wid] = sum;
    __syncthreads();
    if (tid < 32) {
        sum = (tid < 8) ? red[tid] : 0.f;
        #pragma unroll
        for (int off = 4; off; off >>= 1)
            sum += __shfl_xor_sync(0xffffffffu, sum, off);
        if (lid == 0) red[0] = sum;
    }
    __syncthreads();
    float inv = 1.f / red[0];
    #pragma unroll
    for (int l = 0; l < 8; l++)
        prow[tid + l * 256] = __float2half(vals[l] * inv);
}

// ---------------- mma.sync fp16 GEMM: 128x128 tile, 3-stage single-sync ---------
// C[M,N] = alpha * A[M,K] @ Bt[N,K]^T (+ epilogue). A, Bt K-major fp16.
// CTA 128x128x32, 256 threads = 8 warps (2m x 4n), warp tile 64x32.
// 3-stage cp.async ring, ONE __syncthreads per k-chunk (CUTLASS multistage):
//   iter i: issue load(i+2) into slot (i+2)%3 (== slot of compute(i-1), safe by
//   end-of-(i-1) barrier) -> compute(i) -> cp_wait<1> (stage i+1 done) -> sync.
// EPI: 0 plain, 1 bias+gelu, 2 bias+add
// CKLAMP (PV): K clamped to rowBase+128 (P[r][c]==0 for c>r) - exact.
// CSKIP (logits): fully-masked tiles return; g_logits stays 0 (zero-init) - exact.
#define SROW   80              // bytes per padded smem row (64B payload, 20-bank stride)
#define TILE_B (128 * SROW)    // 10240 per operand tile
#define STG    (2 * TILE_B)    // A + B per stage = 20480
#define NSTG   3               // 61440 B total

template<int EPI, int CKLAMP, int CSKIP, typename CT>
__global__ __launch_bounds__(256)
void hgemm(const __half* __restrict__ A, const __half* __restrict__ Bt,
           CT* __restrict__ C, const float* __restrict__ bias,
           const float* __restrict__ add,
           int K, int lda, int ldb, int ldc,
           long long sAb, long long sAh, long long sBb, long long sBh,
           long long sCb, long long sCh, int hdiv, float alpha) {
    extern __shared__ __align__(16) char smem[];       // NSTG * STG
    const uint32_t sbase = smem_u32(smem);
    int tid = threadIdx.x, wid = tid >> 5, lid = tid & 31;

    int rowBase = blockIdx.y * 128;
    int colBase = blockIdx.x * 128;
    if (CSKIP && colBase > rowBase + 127) return;   // fully-masked logit tile

    int z = blockIdx.z, bb = z / hdiv, hh = z % hdiv;
    A  += bb * sAb + hh * sAh;
    Bt += bb * sBb + hh * sBh;
    C  += bb * sCb + hh * sCh;

    int wm = (wid >> 2) * 64;
    int wn = (wid & 3) * 32;

    float acc[4][4][4];
    #pragma unroll
    for (int i = 0; i < 4; i++)
        #pragma unroll
        for (int j = 0; j < 4; j++)
            #pragma unroll
            for (int c = 0; c < 4; c++) acc[i][j][c] = 0.f;

    int Keff = CKLAMP ? min(K, rowBase + 128) : K;
    const int NC = Keff >> 5;
    auto stage_load = [&](int st, int k0) {
        uint32_t base = sbase + st * STG;
        #pragma unroll
        for (int l = 0; l < 4; l++) {
            int c = tid + l * 256;
            int r  = (c & 511) >> 2;
            int kc = c & 3;
            if (c < 512)
                cp_async16(base + r * SROW + kc * 16,
                           A + (size_t)(rowBase + r) * lda + k0 + kc * 8);
            else
                cp_async16(base + TILE_B + r * SROW + kc * 16,
                           Bt + (size_t)(colBase + r) * ldb + k0 + kc * 8);
        }
        cp_commit();
    };

    // prologue: stages 0 and 1 in flight; wait for stage 0, make visible
    stage_load(0, 0);
    if (NC > 1) stage_load(1, 32); else cp_commit();
    cp_wait<1>();
    __syncthreads();

    for (int i = 0; i < NC; i++) {
        if (i + 2 < NC) stage_load((i + 2) % 3, (i + 2) << 5);
        else            cp_commit();                 // keep group count exact

        uint32_t abase = sbase + (i % 3) * STG;
        uint32_t bbase = abase + TILE_B;
        int which = lid >> 3, rim = lid & 7;

        #pragma unroll
        for (int ks = 0; ks < 2; ks++) {
            uint32_t a[4][4];
            #pragma unroll
            for (int mf = 0; mf < 4; mf++) {
                int r = wm + mf * 16 + ((which & 1) << 3) + rim;
                uint32_t addr = abase + r * SROW + ks * 32 + ((which >> 1) << 4);
                ldsm_x4(a[mf][0], a[mf][1], a[mf][2], a[mf][3], addr);
            }
            uint32_t b[4][2];
            #pragma unroll
            for (int np = 0; np < 2; np++) {
                int n = wn + np * 16 + ((which >> 1) << 3) + rim;
                uint32_t addr = bbase + n * SROW + ks * 32 + ((which & 1) << 4);
                uint32_t r0, r1, r2, r3;
                ldsm_x4(r0, r1, r2, r3, addr);
                b[np * 2][0] = r0; b[np * 2][1] = r1;
                b[np * 2 + 1][0] = r2; b[np * 2 + 1][1] = r3;
            }
            #pragma unroll
            for (int mf = 0; mf < 4; mf++)
                #pragma unroll
                for (int nf = 0; nf < 4; nf++)
                    mma16816(acc[mf][nf][0], acc[mf][nf][1], acc[mf][nf][2], acc[mf][nf][3],
                             a[mf][0], a[mf][1], a[mf][2], a[mf][3],
                             b[nf][0], b[nf][1]);
        }

        cp_wait<1>();        // stage i+1 resident
        __syncthreads();     // visible to all; compute(i) done everywhere
    }

    // epilogue: fragment -> gmem (c0,c1 at row lid/4; c2,c3 at row lid/4+8)
    #pragma unroll
    for (int mf = 0; mf < 4; mf++) {
        #pragma unroll
        for (int nf = 0; nf < 4; nf++) {
            int col = colBase + wn + nf * 8 + (lid & 3) * 2;
            #pragma unroll
            for (int h = 0; h < 2; h++) {
                int row = rowBase + wm + mf * 16 + (lid >> 2) + h * 8;
                #pragma unroll
                for (int e = 0; e < 2; e++) {
                    float v = acc[mf][nf][h * 2 + e] * alpha;
                    int cc = col + e;
                    if (EPI == 1) { v += bias[cc]; v = gelu_tanh(v); }
                    if (EPI == 2) { v += bias[cc] + add[(size_t)row * ldc + cc]; }
                    if (sizeof(CT) == 2)
                        *reinterpret_cast<__half*>(&C[(size_t)row * ldc + cc]) = __float2half(v);
                    else
                        *reinterpret_cast<float*>(&C[(size_t)row * ldc + cc]) = v;
                }
            }
        }
    }
}

// ---------------- launch --------------------------------------------------------
static void* symp(const void* s) { void* p = nullptr; cudaGetSymbolAddress(&p, s); return p; }

extern "C" void kernel_launch(void* const* d_in, const int* in_sizes, int n_in,
                              void* d_out, int out_size) {
    (void)in_sizes; (void)n_in; (void)out_size;
    const float* x         = (const float*)d_in[0];
    const float* attn_bias = (const float*)d_in[1];
    const float* ln_scale  = (const float*)d_in[2];
    const float* ln_offset = (const float*)d_in[3];
    const float* wq        = (const float*)d_in[4];
    const float* wk        = (const float*)d_in[5];
    const float* wv        = (const float*)d_in[6];
    const float* wo        = (const float*)d_in[7];
    const float* w_fc_in   = (const float*)d_in[8];
    const float* b_fc_in   = (const float*)d_in[9];
    const float* w_fc_out  = (const float*)d_in[10];
    const float* b_fc_out  = (const float*)d_in[11];
    float* out = (float*)d_out;

    __half* xn16  = (__half*)symp(g_xn16);
    float*  qkv   = (float*)symp(g_qkv);
    __half* q16   = (__half*)symp(g_q16);
    __half* k16   = (__half*)symp(g_k16);
    __half* v16t  = (__half*)symp(g_v16t);
    float*  lg    = (float*)symp(g_logits);
    __half* p16   = (__half*)symp(g_p16);
    __half* av16  = (__half*)symp(g_av16);
    float*  ao    = (float*)symp(g_ao);
    __half* h16   = (__half*)symp(g_h16);
    __half* wqkvt = (__half*)symp(g_wqkvt);
    __half* wot   = (__half*)symp(g_wot);
    __half* wfit  = (__half*)symp(g_wfit);
    __half* wfot  = (__half*)symp(g_wfot);

    const int SMN = NSTG * STG;   // 61440
    cudaFuncSetAttribute(hgemm<0, 0, 0, float >, cudaFuncAttributeMaxDynamicSharedMemorySize, SMN);
    cudaFuncSetAttribute(hgemm<0, 0, 1, float >, cudaFuncAttributeMaxDynamicSharedMemorySize, SMN);
    cudaFuncSetAttribute(hgemm<0, 1, 0, __half>, cudaFuncAttributeMaxDynamicSharedMemorySize, SMN);
    cudaFuncSetAttribute(hgemm<1, 0, 0, __half>, cudaFuncAttributeMaxDynamicSharedMemorySize, SMN);
    cudaFuncSetAttribute(hgemm<2, 0, 0, float >, cudaFuncAttributeMaxDynamicSharedMemorySize, SMN);

    dim3 tb(32, 8), blk(256);

    sincos_kernel<<<(SEQ * HALFD + 255) / 256, 256>>>();
    // weight transposes -> fp16 K-major
    tconv_kernel<<<dim3(D_MODEL / 32, D_MODEL / 32), tb>>>(wq, wqkvt + 0 * (size_t)D_MODEL * D_MODEL, D_MODEL, D_MODEL);
    tconv_kernel<<<dim3(D_MODEL / 32, D_MODEL / 32), tb>>>(wk, wqkvt + 1 * (size_t)D_MODEL * D_MODEL, D_MODEL, D_MODEL);
    tconv_kernel<<<dim3(D_MODEL / 32, D_MODEL / 32), tb>>>(wv, wqkvt + 2 * (size_t)D_MODEL * D_MODEL, D_MODEL, D_MODEL);
    tconv_kernel<<<dim3(D_MODEL / 32, D_MODEL / 32), tb>>>(wo, wot, D_MODEL, D_MODEL);
    tconv_kernel<<<dim3(D_FF / 32, D_MODEL / 32), tb>>>(w_fc_in, wfit, D_MODEL, D_FF);
    tconv_kernel<<<dim3(D_MODEL / 32, D_FF / 32), tb>>>(w_fc_out, wfot, D_FF, D_MODEL);

    layernorm_kernel<<<MROWS, 256>>>(x, ln_scale, ln_offset);

    // fused QKV: z selects weight/output
    hgemm<0, 0, 0, float><<<dim3(D_MODEL / 128, MROWS / 128, 3), blk, SMN>>>(
        xn16, wqkvt, qkv, nullptr, nullptr,
        D_MODEL, D_MODEL, D_MODEL, D_MODEL,
        0, 0, (long long)D_MODEL * D_MODEL, 0, (long long)MROWS * D_MODEL, 0, 1, 1.f);

    rotary_kernel<<<(MROWS * N_HEADS * HALFD + 255) / 256, 256>>>(
        qkv, qkv + (size_t)MROWS * D_MODEL);
    vtrans_kernel<<<dim3(SEQ / 32, DPH / 32, BH), tb>>>(qkv + 2 * (size_t)MROWS * D_MODEL);

    // logits[bh] = q16 @ k16^T / sqrt(dph); fully-masked tiles early-return
    hgemm<0, 0, 1, float><<<dim3(SEQ / 128, SEQ / 128, BH), blk, SMN>>>(
        q16, k16, lg, nullptr, nullptr,
        DPH, D_MODEL, D_MODEL, SEQ,
        (long long)SEQ * D_MODEL, (long long)DPH,
        (long long)SEQ * D_MODEL, (long long)DPH,
        (long long)N_HEADS * SEQ * SEQ, (long long)SEQ * SEQ,
        N_HEADS, 0.08838834764831845f);

    softmax_kernel<<<BH * SEQ, 256>>>(attn_bias);

    // attn_vec[bh] = P @ V, causal K-clamp (exact)
    hgemm<0, 1, 0, __half><<<dim3(DPH / 128, SEQ / 128, BH), blk, SMN>>>(
        p16, v16t, av16, nullptr, nullptr,
        SEQ, SEQ, SEQ, D_MODEL,
        (long long)N_HEADS * SEQ * SEQ, (long long)SEQ * SEQ,
        (long long)N_HEADS * DPH * SEQ, (long long)DPH * SEQ,
        (long long)SEQ * D_MODEL, (long long)DPH,
        N_HEADS, 1.f);

    // attn_out = attn_vec @ wo
    hgemm<0, 0, 0, float><<<dim3(D_MODEL / 128, MROWS / 128, 1), blk, SMN>>>(
        av16, wot, ao, nullptr, nullptr,
        D_MODEL, D_MODEL, D_MODEL, D_MODEL,
        0, 0, 0, 0, 0, 0, 1, 1.f);

    // h = gelu(xn @ w_fc_in + b_fc_in)  -> fp16
    hgemm<1, 0, 0, __half><<<dim3(D_FF / 128, MROWS / 128, 1), blk, SMN>>>(
        xn16, wfit, h16, b_fc_in, nullptr,
        D_MODEL, D_MODEL, D_MODEL, D_FF,
        0, 0, 0, 0, 0, 0, 1, 1.f);

    // out = h @ w_fc_out + b_fc_out + attn_out
    hgemm<2, 0, 0, float><<<dim3(D_MODEL / 128, MROWS / 128, 1), blk, SMN>>>(
        h16, wfot, out, b_fc_out, ao,
        D_FF, D_FF, D_FF, D_MODEL,
        0, 0, 0, 0, 0, 0, 1, 1.f);
}

// round 17
// speedup vs baseline: 1.2284x; 1.0095x over previous
#include <cuda_runtime.h>
#include <cuda_fp16.h>
#include <math.h>
#include <stdint.h>

#define D_MODEL 2048
#define N_HEADS 16
#define DPH     128
#define D_FF    8192
#define BATCH   2
#define SEQ     2048
#define MROWS   (BATCH*SEQ)
#define HALFD   (DPH/2)
#define BH      (BATCH*N_HEADS)

// ---------------- scratch (static device arrays; no cudaMalloc) ----------------
// NOTE: g_logits is zero-initialized at module load; fully-masked logit tiles are
// never written by any kernel, so softmax reads exact 0 there (see causal skip).
__device__ __half g_xn16[(size_t)MROWS*D_MODEL];
__device__ float  g_qkv [(size_t)3*MROWS*D_MODEL];
__device__ __half g_q16 [(size_t)MROWS*D_MODEL];
__device__ __half g_k16 [(size_t)MROWS*D_MODEL];
__device__ __half g_v16t[(size_t)BH*DPH*SEQ];
__device__ float  g_logits[(size_t)BH*SEQ*SEQ];
__device__ __half g_p16 [(size_t)BH*SEQ*SEQ];
__device__ __half g_av16[(size_t)MROWS*D_MODEL];
__device__ float  g_ao  [(size_t)MROWS*D_MODEL];
__device__ __half g_h16 [(size_t)MROWS*D_FF];
__device__ __half g_wqkvt[(size_t)3*D_MODEL*D_MODEL];
__device__ __half g_wot [(size_t)D_MODEL*D_MODEL];
__device__ __half g_wfit[(size_t)D_FF*D_MODEL];
__device__ __half g_wfot[(size_t)D_MODEL*D_FF];
__device__ float2 g_sincos[(size_t)SEQ*HALFD];

// ---------------- family-portable PTX helpers -----------------------------------
__device__ __forceinline__ uint32_t smem_u32(const void* p) {
    uint32_t a;
    asm("{ .reg .u64 t; cvta.to.shared.u64 t, %1; cvt.u32.u64 %0, t; }" : "=r"(a) : "l"(p));
    return a;
}
__device__ __forceinline__ void cp_async16(uint32_t saddr, const void* gptr) {
    asm volatile("cp.async.cg.shared.global [%0], [%1], 16;" :: "r"(saddr), "l"(gptr));
}
__device__ __forceinline__ void cp_commit() {
    asm volatile("cp.async.commit_group;" ::: "memory");
}
template<int N>
__device__ __forceinline__ void cp_wait() {
    asm volatile("cp.async.wait_group %0;" :: "n"(N) : "memory");
}
__device__ __forceinline__ void ldsm_x4(uint32_t& r0, uint32_t& r1, uint32_t& r2, uint32_t& r3,
                                        uint32_t addr) {
    asm volatile("ldmatrix.sync.aligned.m8n8.x4.shared.b16 {%0,%1,%2,%3}, [%4];"
        : "=r"(r0), "=r"(r1), "=r"(r2), "=r"(r3) : "r"(addr));
}
__device__ __forceinline__ void mma16816(float& c0, float& c1, float& c2, float& c3,
                                         uint32_t a0, uint32_t a1, uint32_t a2, uint32_t a3,
                                         uint32_t b0, uint32_t b1) {
    asm volatile("mma.sync.aligned.m16n8k16.row.col.f32.f16.f16.f32 "
        "{%0,%1,%2,%3}, {%4,%5,%6,%7}, {%8,%9}, {%0,%1,%2,%3};"
        : "+f"(c0), "+f"(c1), "+f"(c2), "+f"(c3)
        : "r"(a0), "r"(a1), "r"(a2), "r"(a3), "r"(b0), "r"(b1));
}

// ---------------- small kernels -------------------------------------------------
__global__ void sincos_kernel() {
    int idx = blockIdx.x * blockDim.x + threadIdx.x;
    if (idx >= SEQ * HALFD) return;
    int t = idx / HALFD, i = idx % HALFD;
    double invf = pow(10000.0, -(2.0 * i) / (double)DPH);
    double ang  = (double)t * invf;
    g_sincos[idx] = make_float2((float)sin(ang), (float)cos(ang));
}

__global__ void layernorm_kernel(const float* __restrict__ x,
                                 const float* __restrict__ scale,
                                 const float* __restrict__ offset) {
    int row = blockIdx.x;
    const float* xr = x + (size_t)row * D_MODEL;
    __half* o = g_xn16 + (size_t)row * D_MODEL;
    float s = 0.f, s2 = 0.f;
    for (int j = threadIdx.x; j < D_MODEL; j += blockDim.x) {
        float v = xr[j]; s += v; s2 += v * v;
    }
    __shared__ float red[64];
    #pragma unroll
    for (int off = 16; off; off >>= 1) {
        s  += __shfl_xor_sync(0xffffffffu, s,  off);
        s2 += __shfl_xor_sync(0xffffffffu, s2, off);
    }
    int wid = threadIdx.x >> 5, lid = threadIdx.x & 31;
    if (lid == 0) { red[wid] = s; red[wid + 32] = s2; }
    __syncthreads();
    if (threadIdx.x < 32) {
        int nw = blockDim.x >> 5;
        s  = (threadIdx.x < nw) ? red[threadIdx.x]      : 0.f;
        s2 = (threadIdx.x < nw) ? red[threadIdx.x + 32] : 0.f;
        #pragma unroll
        for (int off = 16; off; off >>= 1) {
            s  += __shfl_xor_sync(0xffffffffu, s,  off);
            s2 += __shfl_xor_sync(0xffffffffu, s2, off);
        }
        if (lid == 0) { red[0] = s; red[1] = s2; }
    }
    __syncthreads();
    float mean = red[0] / D_MODEL;
    float var  = red[1] / D_MODEL - mean * mean;
    float r    = rsqrtf(var + 1e-5f);
    for (int j = threadIdx.x; j < D_MODEL; j += blockDim.x)
        o[j] = __float2half(scale[j] * r * (xr[j] - mean) + offset[j]);
}

// rotary: fp32 q/k -> fp16 q16/k16
__global__ void rotary_kernel(const float* __restrict__ q, const float* __restrict__ k) {
    int idx = blockIdx.x * blockDim.x + threadIdx.x;
    if (idx >= MROWS * N_HEADS * HALFD) return;
    int half = idx % HALFD;
    int rest = idx / HALFD;
    int h    = rest % N_HEADS;
    int row  = rest / N_HEADS;
    int t    = row % SEQ;
    float2 sc = g_sincos[t * HALFD + half];
    size_t base = (size_t)row * D_MODEL + h * DPH + 2 * half;
    float q0 = q[base], q1 = q[base + 1];
    g_q16[base]     = __float2half(q0 * sc.y - q1 * sc.x);
    g_q16[base + 1] = __float2half(q1 * sc.y + q0 * sc.x);
    float k0 = k[base], k1 = k[base + 1];
    g_k16[base]     = __float2half(k0 * sc.y - k1 * sc.x);
    g_k16[base + 1] = __float2half(k1 * sc.y + k0 * sc.x);
}

// weight transpose+convert: in[R][C] fp32 -> out[C][R] fp16
__global__ void tconv_kernel(const float* __restrict__ in, __half* __restrict__ out,
                             int R, int C) {
    __shared__ float t[32][33];
    int bx = blockIdx.x * 32, by = blockIdx.y * 32;
    int tx = threadIdx.x, ty = threadIdx.y;
    #pragma unroll
    for (int i = 0; i < 4; i++)
        t[ty + i * 8][tx] = in[(size_t)(by + ty + i * 8) * C + bx + tx];
    __syncthreads();
    #pragma unroll
    for (int i = 0; i < 4; i++)
        out[(size_t)(bx + ty + i * 8) * R + by + tx] = __float2half(t[tx][ty + i * 8]);
}

// V transpose: fp32 [b*S+t][h*128+d] -> v16t [bh][d][t] fp16
__global__ void vtrans_kernel(const float* __restrict__ v) {
    __shared__ float t[32][33];
    int z = blockIdx.z, bb = z >> 4, hh = z & 15;
    int tb = blockIdx.x * 32, db = blockIdx.y * 32;
    int tx = threadIdx.x, ty = threadIdx.y;
    #pragma unroll
    for (int i = 0; i < 4; i++)
        t[ty + i * 8][tx] = v[(size_t)(bb * SEQ + tb + ty + i * 8) * D_MODEL + hh * DPH + db + tx];
    __syncthreads();
    #pragma unroll
    for (int i = 0; i < 4; i++)
        g_v16t[((size_t)z * DPH + db + ty + i * 8) * SEQ + tb + tx] = __float2half(t[tx][ty + i * 8]);
}

__device__ __forceinline__ float gelu_tanh(float x) {
    float x3 = x * x * x;
    float t = tanhf(0.7978845608028654f * (x + 0.044715f * x3));
    return 0.5f * x * (1.f + t);
}

// masked softmax: fp32 logits (+bias, causal) -> fp16 probs
// chunks fully beyond the diagonal are skipped (exp(-1e10) == 0 in fp32: exact)
__global__ __launch_bounds__(256)
void softmax_kernel(const float* __restrict__ attn_bias) {
    long long r = blockIdx.x;
    int i = (int)(r % SEQ);
    const float* row = g_logits + r * SEQ;
    __half* prow = g_p16 + r * SEQ;
    const float* brow = attn_bias + (size_t)i * SEQ;
    int tid = threadIdx.x;
    float vals[8];
    float mx = -INFINITY;
    #pragma unroll
    for (int l = 0; l < 8; l++) {
        int j = tid + l * 256;
        float v;
        if (l * 256 <= i) {                 // uniform per block: no divergence
            v = row[j] + brow[j];
            if (j > i) v += -1e10f;
        } else {
            v = -1e30f;                     // exp -> exactly 0
        }
        vals[l] = v;
        mx = fmaxf(mx, v);
    }
    __shared__ float red[32];
    #pragma unroll
    for (int off = 16; off; off >>= 1)
        mx = fmaxf(mx, __shfl_xor_sync(0xffffffffu, mx, off));
    int wid = tid >> 5, lid = tid & 31;
    if (lid == 0) red[wid] = mx;
    __syncthreads();
    if (tid < 32) {
        mx = (tid < 8) ? red[tid] : -INFINITY;
        #pragma unroll
        for (int off = 4; off; off >>= 1)
            mx = fmaxf(mx, __shfl_xor_sync(0xffffffffu, mx, off));
        if (lid == 0) red[0] = mx;
    }
    __syncthreads();
    mx = red[0];
    float sum = 0.f;
    #pragma unroll
    for (int l = 0; l < 8; l++) { vals[l] = expf(vals[l] - mx); sum += vals[l]; }
    #pragma unroll
    for (int off = 16; off; off >>= 1)
        sum += __shfl_xor_sync(0xffffffffu, sum, off);
    if (lid == 0) red[wid] = sum;
    __syncthreads();
    if (tid < 32) {
        sum = (tid < 8) ? red[tid] : 0.f;
        #pragma unroll
        for (int off = 4; off; off >>= 1)
            sum += __shfl_xor_sync(0xffffffffu, sum, off);
        if (lid == 0) red[0] = sum;
    }
    __syncthreads();
    float inv = 1.f / red[0];
    #pragma unroll
    for (int l = 0; l < 8; l++)
        prow[tid + l * 256] = __float2half(vals[l] * inv);
}

// ---------------- mma.sync fp16 GEMM: 128x128 tile, BK=64, 3-stage single-sync --
// C[M,N] = alpha * A[M,K] @ Bt[N,K]^T (+ epilogue). A, Bt K-major fp16.
// CTA 128x128x64, 256 threads = 8 warps (2m x 4n), warp tile 64x32.
// 3-stage cp.async ring, ONE __syncthreads per k64-chunk (CUTLASS multistage):
//   iter i: issue load(i+2) into slot (i+2)%3 (== slot of compute(i-1), safe by
//   end-of-(i-1) barrier) -> compute(i): 4 k16 steps -> cp_wait<1> -> sync.
// SROW=144 (128B payload + 16 pad): bank stride 36 -> 8 ldmatrix row addrs hit
// banks {0,4,...,28}, conflict-free. k16 accumulation order identical to BK=32
// version -> bit-exact results.
// EPI: 0 plain, 1 bias+gelu, 2 bias+add
// CKLAMP (PV): K clamped to rowBase+128 (P[r][c]==0 for c>r) - exact.
// CSKIP (logits): fully-masked tiles return; g_logits stays 0 (zero-init) - exact.
#define SROW   144             // bytes per padded smem row (128B payload)
#define TILE_B (128 * SROW)    // 18432 per operand tile
#define STG    (2 * TILE_B)    // A + B per stage = 36864
#define NSTG   3               // 110592 B total; 2 CTAs/SM = 223KB <= 228KB

template<int EPI, int CKLAMP, int CSKIP, typename CT>
__global__ __launch_bounds__(256)
void hgemm(const __half* __restrict__ A, const __half* __restrict__ Bt,
           CT* __restrict__ C, const float* __restrict__ bias,
           const float* __restrict__ add,
           int K, int lda, int ldb, int ldc,
           long long sAb, long long sAh, long long sBb, long long sBh,
           long long sCb, long long sCh, int hdiv, float alpha) {
    extern __shared__ __align__(16) char smem[];       // NSTG * STG
    const uint32_t sbase = smem_u32(smem);
    int tid = threadIdx.x, wid = tid >> 5, lid = tid & 31;

    int rowBase = blockIdx.y * 128;
    int colBase = blockIdx.x * 128;
    if (CSKIP && colBase > rowBase + 127) return;   // fully-masked logit tile

    int z = blockIdx.z, bb = z / hdiv, hh = z % hdiv;
    A  += bb * sAb + hh * sAh;
    Bt += bb * sBb + hh * sBh;
    C  += bb * sCb + hh * sCh;

    int wm = (wid >> 2) * 64;
    int wn = (wid & 3) * 32;

    float acc[4][4][4];
    #pragma unroll
    for (int i = 0; i < 4; i++)
        #pragma unroll
        for (int j = 0; j < 4; j++)
            #pragma unroll
            for (int c = 0; c < 4; c++) acc[i][j][c] = 0.f;

    int Keff = CKLAMP ? min(K, rowBase + 128) : K;
    const int NC = Keff >> 6;                        // k64 chunks
    auto stage_load = [&](int st, int k0) {
        uint32_t base = sbase + st * STG;
        // 2048 16B chunks per stage (A 1024 + B 1024), 8 per thread
        #pragma unroll
        for (int l = 0; l < 8; l++) {
            int c = tid + l * 256;
            int r  = (c & 1023) >> 3;
            int kc = c & 7;
            if (c < 1024)
                cp_async16(base + r * SROW + kc * 16,
                           A + (size_t)(rowBase + r) * lda + k0 + kc * 8);
            else
                cp_async16(base + TILE_B + r * SROW + kc * 16,
                           Bt + (size_t)(colBase + r) * ldb + k0 + kc * 8);
        }
        cp_commit();
    };

    // prologue: stages 0 and 1 in flight; wait for stage 0, make visible
    stage_load(0, 0);
    if (NC > 1) stage_load(1, 64); else cp_commit();
    cp_wait<1>();
    __syncthreads();

    for (int i = 0; i < NC; i++) {
        if (i + 2 < NC) stage_load((i + 2) % 3, (i + 2) << 6);
        else            cp_commit();                 // keep group count exact

        uint32_t abase = sbase + (i % 3) * STG;
        uint32_t bbase = abase + TILE_B;
        int which = lid >> 3, rim = lid & 7;

        #pragma unroll
        for (int ks = 0; ks < 4; ks++) {
            uint32_t a[4][4];
            #pragma unroll
            for (int mf = 0; mf < 4; mf++) {
                int r = wm + mf * 16 + ((which & 1) << 3) + rim;
                uint32_t addr = abase + r * SROW + ks * 32 + ((which >> 1) << 4);
                ldsm_x4(a[mf][0], a[mf][1], a[mf][2], a[mf][3], addr);
            }
            uint32_t b[4][2];
            #pragma unroll
            for (int np = 0; np < 2; np++) {
                int n = wn + np * 16 + ((which >> 1) << 3) + rim;
                uint32_t addr = bbase + n * SROW + ks * 32 + ((which & 1) << 4);
                uint32_t r0, r1, r2, r3;
                ldsm_x4(r0, r1, r2, r3, addr);
                b[np * 2][0] = r0; b[np * 2][1] = r1;
                b[np * 2 + 1][0] = r2; b[np * 2 + 1][1] = r3;
            }
            #pragma unroll
            for (int mf = 0; mf < 4; mf++)
                #pragma unroll
                for (int nf = 0; nf < 4; nf++)
                    mma16816(acc[mf][nf][0], acc[mf][nf][1], acc[mf][nf][2], acc[mf][nf][3],
                             a[mf][0], a[mf][1], a[mf][2], a[mf][3],
                             b[nf][0], b[nf][1]);
        }

        cp_wait<1>();        // stage i+1 resident
        __syncthreads();     // visible to all; compute(i) done everywhere
    }

    // epilogue: fragment -> gmem (c0,c1 at row lid/4; c2,c3 at row lid/4+8)
    #pragma unroll
    for (int mf = 0; mf < 4; mf++) {
        #pragma unroll
        for (int nf = 0; nf < 4; nf++) {
            int col = colBase + wn + nf * 8 + (lid & 3) * 2;
            #pragma unroll
            for (int h = 0; h < 2; h++) {
                int row = rowBase + wm + mf * 16 + (lid >> 2) + h * 8;
                #pragma unroll
                for (int e = 0; e < 2; e++) {
                    float v = acc[mf][nf][h * 2 + e] * alpha;
                    int cc = col + e;
                    if (EPI == 1) { v += bias[cc]; v = gelu_tanh(v); }
                    if (EPI == 2) { v += bias[cc] + add[(size_t)row * ldc + cc]; }
                    if (sizeof(CT) == 2)
                        *reinterpret_cast<__half*>(&C[(size_t)row * ldc + cc]) = __float2half(v);
                    else
                        *reinterpret_cast<float*>(&C[(size_t)row * ldc + cc]) = v;
                }
            }
        }
    }
}

// ---------------- launch --------------------------------------------------------
static void* symp(const void* s) { void* p = nullptr; cudaGetSymbolAddress(&p, s); return p; }

extern "C" void kernel_launch(void* const* d_in, const int* in_sizes, int n_in,
                              void* d_out, int out_size) {
    (void)in_sizes; (void)n_in; (void)out_size;
    const float* x         = (const float*)d_in[0];
    const float* attn_bias = (const float*)d_in[1];
    const float* ln_scale  = (const float*)d_in[2];
    const float* ln_offset = (const float*)d_in[3];
    const float* wq        = (const float*)d_in[4];
    const float* wk        = (const float*)d_in[5];
    const float* wv        = (const float*)d_in[6];
    const float* wo        = (const float*)d_in[7];
    const float* w_fc_in   = (const float*)d_in[8];
    const float* b_fc_in   = (const float*)d_in[9];
    const float* w_fc_out  = (const float*)d_in[10];
    const float* b_fc_out  = (const float*)d_in[11];
    float* out = (float*)d_out;

    __half* xn16  = (__half*)symp(g_xn16);
    float*  qkv   = (float*)symp(g_qkv);
    __half* q16   = (__half*)symp(g_q16);
    __half* k16   = (__half*)symp(g_k16);
    __half* v16t  = (__half*)symp(g_v16t);
    float*  lg    = (float*)symp(g_logits);
    __half* p16   = (__half*)symp(g_p16);
    __half* av16  = (__half*)symp(g_av16);
    float*  ao    = (float*)symp(g_ao);
    __half* h16   = (__half*)symp(g_h16);
    __half* wqkvt = (__half*)symp(g_wqkvt);
    __half* wot   = (__half*)symp(g_wot);
    __half* wfit  = (__half*)symp(g_wfit);
    __half* wfot  = (__half*)symp(g_wfot);

    const int SMN = NSTG * STG;   // 110592
    cudaFuncSetAttribute(hgemm<0, 0, 0, float >, cudaFuncAttributeMaxDynamicSharedMemorySize, SMN);
    cudaFuncSetAttribute(hgemm<0, 0, 1, float >, cudaFuncAttributeMaxDynamicSharedMemorySize, SMN);
    cudaFuncSetAttribute(hgemm<0, 1, 0, __half>, cudaFuncAttributeMaxDynamicSharedMemorySize, SMN);
    cudaFuncSetAttribute(hgemm<1, 0, 0, __half>, cudaFuncAttributeMaxDynamicSharedMemorySize, SMN);
    cudaFuncSetAttribute(hgemm<2, 0, 0, float >, cudaFuncAttributeMaxDynamicSharedMemorySize, SMN);

    dim3 tb(32, 8), blk(256);

    sincos_kernel<<<(SEQ * HALFD + 255) / 256, 256>>>();
    // weight transposes -> fp16 K-major
    tconv_kernel<<<dim3(D_MODEL / 32, D_MODEL / 32), tb>>>(wq, wqkvt + 0 * (size_t)D_MODEL * D_MODEL, D_MODEL, D_MODEL);
    tconv_kernel<<<dim3(D_MODEL / 32, D_MODEL / 32), tb>>>(wk, wqkvt + 1 * (size_t)D_MODEL * D_MODEL, D_MODEL, D_MODEL);
    tconv_kernel<<<dim3(D_MODEL / 32, D_MODEL / 32), tb>>>(wv, wqkvt + 2 * (size_t)D_MODEL * D_MODEL, D_MODEL, D_MODEL);
    tconv_kernel<<<dim3(D_MODEL / 32, D_MODEL / 32), tb>>>(wo, wot, D_MODEL, D_MODEL);
    tconv_kernel<<<dim3(D_FF / 32, D_MODEL / 32), tb>>>(w_fc_in, wfit, D_MODEL, D_FF);
    tconv_kernel<<<dim3(D_MODEL / 32, D_FF / 32), tb>>>(w_fc_out, wfot, D_FF, D_MODEL);

    layernorm_kernel<<<MROWS, 256>>>(x, ln_scale, ln_offset);

    // fused QKV: z selects weight/output
    hgemm<0, 0, 0, float><<<dim3(D_MODEL / 128, MROWS / 128, 3), blk, SMN>>>(
        xn16, wqkvt, qkv, nullptr, nullptr,
        D_MODEL, D_MODEL, D_MODEL, D_MODEL,
        0, 0, (long long)D_MODEL * D_MODEL, 0, (long long)MROWS * D_MODEL, 0, 1, 1.f);

    rotary_kernel<<<(MROWS * N_HEADS * HALFD + 255) / 256, 256>>>(
        qkv, qkv + (size_t)MROWS * D_MODEL);
    vtrans_kernel<<<dim3(SEQ / 32, DPH / 32, BH), tb>>>(qkv + 2 * (size_t)MROWS * D_MODEL);

    // logits[bh] = q16 @ k16^T / sqrt(dph); fully-masked tiles early-return
    hgemm<0, 0, 1, float><<<dim3(SEQ / 128, SEQ / 128, BH), blk, SMN>>>(
        q16, k16, lg, nullptr, nullptr,
        DPH, D_MODEL, D_MODEL, SEQ,
        (long long)SEQ * D_MODEL, (long long)DPH,
        (long long)SEQ * D_MODEL, (long long)DPH,
        (long long)N_HEADS * SEQ * SEQ, (long long)SEQ * SEQ,
        N_HEADS, 0.08838834764831845f);

    softmax_kernel<<<BH * SEQ, 256>>>(attn_bias);

    // attn_vec[bh] = P @ V, causal K-clamp (exact)
    hgemm<0, 1, 0, __half><<<dim3(DPH / 128, SEQ / 128, BH), blk, SMN>>>(
        p16, v16t, av16, nullptr, nullptr,
        SEQ, SEQ, SEQ, D_MODEL,
        (long long)N_HEADS * SEQ * SEQ, (long long)SEQ * SEQ,
        (long long)N_HEADS * DPH * SEQ, (long long)DPH * SEQ,
        (long long)SEQ * D_MODEL, (long long)DPH,
        N_HEADS, 1.f);

    // attn_out = attn_vec @ wo
    hgemm<0, 0, 0, float><<<dim3(D_MODEL / 128, MROWS / 128, 1), blk, SMN>>>(
        av16, wot, ao, nullptr, nullptr,
        D_MODEL, D_MODEL, D_MODEL, D_MODEL,
        0, 0, 0, 0, 0, 0, 1, 1.f);

    // h = gelu(xn @ w_fc_in + b_fc_in)  -> fp16
    hgemm<1, 0, 0, __half><<<dim3(D_FF / 128, MROWS / 128, 1), blk, SMN>>>(
        xn16, wfit, h16, b_fc_in, nullptr,
        D_MODEL, D_MODEL, D_MODEL, D_FF,
        0, 0, 0, 0, 0, 0, 1, 1.f);

    // out = h @ w_fc_out + b_fc_out + attn_out
    hgemm<2, 0, 0, float><<<dim3(D_MODEL / 128, MROWS / 128, 1), blk, SMN>>>(
        h16, wfot, out, b_fc_out, ao,
        D_FF, D_FF, D_FF, D_MODEL,
        0, 0, 0, 0, 0, 0, 1, 1.f);
}